// round 6
// baseline (speedup 1.0000x reference)
#include <cuda_runtime.h>

#define EPS 1e-10f
#define NSTATE 68
#define NF4 17                      // 68 floats = 17 float4
#define COLSTRIDE 33                // 33 % 8 == 1 -> conflict-free bank walk
#define WARPS_PER_BLOCK 4
#define THREADS (WARPS_PER_BLOCK * 32)

// Compute the 68 derivatives for one row. sp = smem param/derived array.
__device__ __forceinline__ void compute_rhs(const float* __restrict__ sp,
                                            const float* ys, float* d) {
    const float ka1 = sp[0], kr1 = sp[1], kc1 = sp[2];
    // Precomputed per-block derived constants:
    const float kBRAF_eff    = sp[75];
    const float tram_ksr     = sp[76];
    const float kmDuspRatio  = sp[77];
    const float kmSprtyRatio = sp[78];
    const float kDimVem      = sp[79];
    const float kParaVem     = sp[80];

    // --- EGFR / Her2 / Her3 receptor modules ---
    d[0] = -ka1*ys[0] + kr1*ys[1];
    d[1] =  ka1*ys[0] - kr1*ys[1] - kc1*ys[1];
    d[2] =  kc1*ys[1] - sp[6]*ys[2] - sp[7]*ys[28]*ys[2];
    d[3] = -sp[31]*ys[3] + kr1*ys[4];
    d[4] =  sp[31]*ys[3] - kr1*ys[4] - kc1*ys[4];
    d[5] =  kc1*ys[4] - sp[6]*ys[5] - sp[7]*ys[28]*ys[5];
    d[6] = -sp[32]*ys[6] + kr1*ys[7];
    d[7] =  sp[32]*ys[6] - kr1*ys[7] - kc1*ys[7];
    d[8] =  kc1*ys[7] - sp[6]*ys[8] - sp[7]*ys[28]*ys[8];

    // --- Shc / Grb2 / Sos / Ras ---
    float a29 = ka1*ys[2]*ys[9];
    d[9]  = -a29;
    d[10] =  a29 - sp[8]*ys[11]*ys[10];
    d[11] = -sp[9]*ys[10]*ys[11];
    d[12] =  sp[10]*ys[10]*ys[2] - sp[11]*ys[26]*ys[12];
    d[13] =  sp[12]*ys[12]*ys[10] - sp[13]*ys[24]*ys[13];
    float s14 = ka1*ys[13]*ys[14];
    d[14] = -s14;
    d[15] =  s14;
    float s16 = ka1*ys[13]*ys[16];
    d[16] = -s16;
    d[17] =  s16;
    float s18 = ka1*ys[13]*ys[18];
    float s19 = ka1*ys[19]*ys[20];
    d[18] = -s18;
    d[19] =  s18 - s19;
    d[20] = -s19;

    // --- RAF with vemurafenib paradox ---
    float paradox   = kParaVem * ys[61];
    float akt_craf  = sp[70]*ys[52]*ys[21];
    float dimF      = kDimVem*ys[24]*ys[21];
    float dimD      = sp[59]*ys[61];
    float craf_fwd  = sp[3]*ys[19]*ys[21];
    float craf_rev  = sp[14]*ys[28]*ys[22];
    float craf_deg  = sp[15]*ys[22]*ys[35];
    float braf_act  = kBRAF_eff*ys[23]*ys[19];
    d[21] = -craf_fwd + craf_rev + craf_deg - dimF + dimD - akt_craf;
    d[22] =  craf_fwd - craf_rev - craf_deg + paradox;
    d[23] = -braf_act - dimF + dimD;
    d[24] =  braf_act - sp[20]*ys[24] - dimF + dimD;
    d[61] =  dimF - dimD - sp[15]*ys[61]*ys[35];

    // --- MEK / ERK ---
    float raf_to_mek = sp[4]*ys[22] + sp[50]*ys[24] + sp[51]*ys[22];
    float ksr_to_mek = sp[52]*ys[60];
    float mek_fwd    = (raf_to_mek + ksr_to_mek)*ys[25];
    float mek_rev    = sp[16]*ys[28]*ys[26];
    float mek_deg    = sp[17]*ys[26]*ys[34];
    d[25] = -mek_fwd + mek_rev + mek_deg;
    d[26] =  mek_fwd - mek_rev - mek_deg;
    float erk_fwd = sp[5]*ys[26]*ys[27];
    float erk_bk  = sp[18]*ys[30]*ys[28] + sp[19]*ys[28]*ys[33] + sp[29]*ys[30]*ys[28];
    d[27] = -erk_fwd + erk_bk;
    d[28] =  erk_fwd - erk_bk;

    // --- DUSP / Sprouty feedback ---
    float denom_dusp = 1.0f + kmDuspRatio*ys[28];
    d[29] = sp[27]*ys[28]/(denom_dusp + EPS) - sp[21]*ys[29]*ys[36] - sp[30]*ys[29]*ys[28];
    d[30] = -sp[21]*ys[29]*ys[30];
    float denom_spry = 1.0f + kmSprtyRatio*ys[28];
    float spry_dn = sp[24]*ys[31]*ys[32];
    d[31] = sp[28]*ys[28]/(denom_spry + EPS) - spry_dn;
    d[32] = -spry_dn;
    d[33] = -sp[19]*ys[28]*ys[33];
    d[34] = -mek_deg;
    d[35] = -craf_deg;
    d[36] = -sp[21]*ys[29]*ys[36];

    // --- IGFR / IRS ---
    d[37] = -ka1*ys[37] + kr1*ys[38];
    d[38] =  ka1*ys[37] - kr1*ys[38] - kc1*ys[38];
    d[39] =  kc1*ys[38] - sp[7]*ys[28]*ys[39];
    float erk_irs = sp[68]*ys[28]*ys[41];
    float s6k_irs = sp[71]*ys[66]*ys[41];
    float irs_fwd = ka1*ys[2]*ys[40];
    d[40] = -irs_fwd + erk_irs + s6k_irs;
    d[41] =  irs_fwd - erk_irs - s6k_irs;

    // --- p85 binding ---
    float gab1 = 1.0f / (1.0f + sp[72]*ys[28]);
    float bE  = sp[33]*ys[2]*ys[42]*gab1;
    float bH2 = sp[34]*ys[5]*ys[42]*gab1;
    float bH3 = sp[35]*ys[8]*ys[42]*gab1;
    float bI  = sp[36]*ys[39]*ys[42];
    float bP  = sp[64]*ys[64]*ys[42];
    float sum_p85c = ys[43] + ys[44] + ys[45] + ys[46] + ys[67];
    float kunb = sp[37];
    d[42] = -bE - bH2 - bH3 - bI - bP + kunb*sum_p85c;
    d[43] = bE  - kunb*ys[43];
    d[44] = bH2 - kunb*ys[44];
    d[45] = bH3 - kunb*ys[45];
    d[46] = bI  - kunb*ys[46];
    d[67] = bP  - kunb*ys[67];

    // --- PI3K / AKT / mTOR axis ---
    float pi3k_act = sp[38]*sum_p85c*ys[47] + sp[67]*ys[15]*ys[47];
    float mtor_fb  = sp[39]*ys[56]*ys[48];
    d[47] = -pi3k_act + mtor_fb;
    d[48] =  pi3k_act - mtor_fb;
    float pip_fwd = sp[40]*ys[48]*ys[49];
    float pip_rev = sp[41]*ys[51]*ys[50];
    d[49] = -pip_fwd + pip_rev;
    d[50] =  pip_fwd - pip_rev;
    d[51] = sp[69]*ys[28] - sp[25]*ys[51];
    float akt_fwd = sp[42]*ys[50]*ys[53];
    float akt_rev = sp[43]*ys[52];
    d[52] =  akt_fwd - akt_rev;
    d[53] = -akt_fwd + akt_rev;
    float tsc = sp[73]*ys[52]*ys[54];
    d[54] = -tsc;
    d[55] =  tsc - sp[25]*ys[55];
    float mtor_fwd = sp[44]*ys[52]*ys[57];
    float mtor_rev = sp[45]*ys[56];
    d[56] =  mtor_fwd - mtor_rev;
    d[57] = -mtor_fwd + mtor_rev;
    float ebp_fwd = sp[46]*ys[56]*ys[58];
    float ebp_rev = sp[47]*ys[59];
    d[58] = -ebp_fwd + ebp_rev;
    d[59] =  ebp_fwd - ebp_rev;

    // --- KSR with trametinib hill factor ---
    float ksr_fwd = sp[48]*ys[19]*ys[62]*tram_ksr;
    float ksr_rev = sp[49]*ys[60];
    d[60] =  ksr_fwd - ksr_rev;
    d[62] = -ksr_fwd + ksr_rev;

    // --- PDGFR ---
    d[63] = -sp[63]*ys[63];
    d[64] =  sp[63]*ys[63] - sp[6]*ys[64];

    // --- S6K ---
    float s6_fwd = sp[65]*ys[56]*ys[65];
    float rsk    = sp[74]*ys[28]*ys[65];
    float s6_rev = sp[66]*ys[66];
    d[65] = -s6_fwd + s6_rev - rsk;
    d[66] =  s6_fwd - s6_rev + rsk;
}

__global__ __launch_bounds__(THREADS, 4)
void mapk_rhs_kernel(const float* __restrict__ y, const float* __restrict__ params,
                     float* __restrict__ out, int n) {
    // Per-warp float4 tile, column-major with stride 33 (conflict-free).
    __shared__ float4 stage[WARPS_PER_BLOCK][NF4 * COLSTRIDE];
    __shared__ float sp[81];   // [0..74] raw params, [75..80] derived

    const int tid  = threadIdx.x;
    const int lane = tid & 31;
    const int warp = tid >> 5;

    // ---- Prologue: params + derived constants into smem (per block) ----
    if (tid < 75) sp[tid] = __ldg(&params[tid]);
    if (tid == 75) {
        float ic50n = __powf(__ldg(&params[61]), __ldg(&params[62]));
        float vemn  = __powf(__ldg(&params[57]), __ldg(&params[62]));
        sp[75] = __ldg(&params[0]) * ic50n / (ic50n + vemn + EPS);   // kBRAF_eff
    }
    if (tid == 76) {
        float ktn = __powf(__ldg(&params[55]), __ldg(&params[56]));
        float tn  = __powf(__ldg(&params[53]), __ldg(&params[56]));
        sp[76] = ktn / (ktn + tn + EPS);                             // tram_ksr
    }
    if (tid == 77) sp[77] = __ldg(&params[27]) / (__ldg(&params[22]) + EPS);
    if (tid == 78) sp[78] = __ldg(&params[28]) / (__ldg(&params[23]) + EPS);
    if (tid == 79) sp[79] = __ldg(&params[58]) * __ldg(&params[57]); // kDimerForm*Vem
    if (tid == 80) sp[80] = __ldg(&params[60]) * __ldg(&params[57]); // kParadoxCRAF*Vem
    __syncthreads();

    const int rowStart = blockIdx.x * THREADS + warp * 32;
    if (rowStart >= n) return;
    const int rowsHere = min(32, n - rowStart);

    float4* sm = stage[warp];

    if (rowsHere == 32) {
        const float4* gsrc = reinterpret_cast<const float4*>(y) + (size_t)rowStart * NF4;

        // ---- Phase 1: coalesced LDG.128 -> transposed smem tile ----
        #pragma unroll
        for (int j = 0; j < NF4; j++) {
            int i = j * 32 + lane;          // f4 index within warp tile
            int r = i / NF4;
            int c = i - r * NF4;
            float4 v = __ldg(&gsrc[i]);
            v.x = fmaxf(v.x, 0.0f);
            v.y = fmaxf(v.y, 0.0f);
            v.z = fmaxf(v.z, 0.0f);
            v.w = fmaxf(v.w, 0.0f);
            sm[c * COLSTRIDE + r] = v;
        }
        __syncwarp();

        // ---- Phase 2: each thread owns row = lane; conflict-free smem access ----
        {
            float ys[NSTATE];
            float4* ysv = reinterpret_cast<float4*>(ys);
            #pragma unroll
            for (int c = 0; c < NF4; c++) ysv[c] = sm[c * COLSTRIDE + lane];

            float d[NSTATE];
            compute_rhs(sp, ys, d);

            const float4* dv = reinterpret_cast<const float4*>(d);
            #pragma unroll
            for (int c = 0; c < NF4; c++) sm[c * COLSTRIDE + lane] = dv[c];
        }
        __syncwarp();

        // ---- Phase 3: transposed smem tile -> coalesced STG.128 ----
        float4* gdst = reinterpret_cast<float4*>(out) + (size_t)rowStart * NF4;
        #pragma unroll
        for (int j = 0; j < NF4; j++) {
            int i = j * 32 + lane;
            int r = i / NF4;
            int c = i - r * NF4;
            gdst[i] = sm[c * COLSTRIDE + r];
        }
    } else {
        // ---- Tail (rows < 32): direct per-row float4 access ----
        if (lane < rowsHere) {
            const int row = rowStart + lane;
            const float4* yv = reinterpret_cast<const float4*>(y) + (size_t)row * NF4;
            float ys[NSTATE];
            float4* ysv = reinterpret_cast<float4*>(ys);
            #pragma unroll
            for (int c = 0; c < NF4; c++) {
                float4 v = __ldg(&yv[c]);
                v.x = fmaxf(v.x, 0.0f);
                v.y = fmaxf(v.y, 0.0f);
                v.z = fmaxf(v.z, 0.0f);
                v.w = fmaxf(v.w, 0.0f);
                ysv[c] = v;
            }
            float d[NSTATE];
            compute_rhs(sp, ys, d);
            float4* ov = reinterpret_cast<float4*>(out) + (size_t)row * NF4;
            const float4* dv = reinterpret_cast<const float4*>(d);
            #pragma unroll
            for (int c = 0; c < NF4; c++) ov[c] = dv[c];
        }
    }
}

extern "C" void kernel_launch(void* const* d_in, const int* in_sizes, int n_in,
                              void* d_out, int out_size) {
    // inputs per metadata order: t (1), y (B*68), params (75)
    const float* y      = (const float*)d_in[1];
    const float* params = (const float*)d_in[2];
    float* out = (float*)d_out;

    int n = in_sizes[1] / NSTATE;   // number of rows (B)

    int blocks = (n + THREADS - 1) / THREADS;
    mapk_rhs_kernel<<<blocks, THREADS>>>(y, params, out, n);
}

// round 7
// speedup vs baseline: 1.0085x; 1.0085x over previous
#include <cuda_runtime.h>

#define EPS 1e-10f
#define NSTATE 68
#define NF4 17                      // 68 floats = 17 float4
#define COLSTRIDE 33                // 33 % 8 == 1 -> conflict-free bank walk
#define WARPS_PER_BLOCK 4
#define THREADS (WARPS_PER_BLOCK * 32)

// Compute the 68 derivatives for one row. p = global params (uniform, L1-hot).
// Params referenced inline so ptxas schedules loads near use under reg pressure.
__device__ __forceinline__ void compute_rhs(const float* __restrict__ p,
                                            const float* ys, float* d) {
    // ---- derived (uniform; approx pow is exact for default 1^1) ----
    const float ic50n     = __powf(p[61], p[62]);
    const float vemn      = __powf(p[57], p[62]);
    const float kBRAF_eff = p[0] * ic50n / (ic50n + vemn + EPS);
    const float ktn       = __powf(p[55], p[56]);
    const float tn        = __powf(p[53], p[56]);
    const float tram_ksr  = ktn / (ktn + tn + EPS);
    const float kmDuspRatio  = p[27] / (p[22] + EPS);
    const float kmSprtyRatio = p[28] / (p[23] + EPS);
    const float kDimVem   = p[58] * p[57];
    const float kParaVem  = p[60] * p[57];

    // --- EGFR / Her2 / Her3 receptor modules ---
    d[0] = -p[0]*ys[0] + p[1]*ys[1];
    d[1] =  p[0]*ys[0] - p[1]*ys[1] - p[2]*ys[1];
    d[2] =  p[2]*ys[1] - p[6]*ys[2] - p[7]*ys[28]*ys[2];
    d[3] = -p[31]*ys[3] + p[1]*ys[4];
    d[4] =  p[31]*ys[3] - p[1]*ys[4] - p[2]*ys[4];
    d[5] =  p[2]*ys[4] - p[6]*ys[5] - p[7]*ys[28]*ys[5];
    d[6] = -p[32]*ys[6] + p[1]*ys[7];
    d[7] =  p[32]*ys[6] - p[1]*ys[7] - p[2]*ys[7];
    d[8] =  p[2]*ys[7] - p[6]*ys[8] - p[7]*ys[28]*ys[8];

    // --- Shc / Grb2 / Sos / Ras ---
    float a29 = p[0]*ys[2]*ys[9];
    d[9]  = -a29;
    d[10] =  a29 - p[8]*ys[11]*ys[10];
    d[11] = -p[9]*ys[10]*ys[11];
    d[12] =  p[10]*ys[10]*ys[2] - p[11]*ys[26]*ys[12];
    d[13] =  p[12]*ys[12]*ys[10] - p[13]*ys[24]*ys[13];
    float s14 = p[0]*ys[13]*ys[14];
    d[14] = -s14;
    d[15] =  s14;
    float s16 = p[0]*ys[13]*ys[16];
    d[16] = -s16;
    d[17] =  s16;
    float s18 = p[0]*ys[13]*ys[18];
    float s19 = p[0]*ys[19]*ys[20];
    d[18] = -s18;
    d[19] =  s18 - s19;
    d[20] = -s19;

    // --- RAF with vemurafenib paradox ---
    float paradox   = kParaVem * ys[61];
    float akt_craf  = p[70]*ys[52]*ys[21];
    float dimF      = kDimVem*ys[24]*ys[21];
    float dimD      = p[59]*ys[61];
    float craf_fwd  = p[3]*ys[19]*ys[21];
    float craf_rev  = p[14]*ys[28]*ys[22];
    float craf_deg  = p[15]*ys[22]*ys[35];
    float braf_act  = kBRAF_eff*ys[23]*ys[19];
    d[21] = -craf_fwd + craf_rev + craf_deg - dimF + dimD - akt_craf;
    d[22] =  craf_fwd - craf_rev - craf_deg + paradox;
    d[23] = -braf_act - dimF + dimD;
    d[24] =  braf_act - p[20]*ys[24] - dimF + dimD;
    d[61] =  dimF - dimD - p[15]*ys[61]*ys[35];

    // --- MEK / ERK ---
    float raf_to_mek = p[4]*ys[22] + p[50]*ys[24] + p[51]*ys[22];
    float ksr_to_mek = p[52]*ys[60];
    float mek_fwd    = (raf_to_mek + ksr_to_mek)*ys[25];
    float mek_rev    = p[16]*ys[28]*ys[26];
    float mek_deg    = p[17]*ys[26]*ys[34];
    d[25] = -mek_fwd + mek_rev + mek_deg;
    d[26] =  mek_fwd - mek_rev - mek_deg;
    float erk_fwd = p[5]*ys[26]*ys[27];
    float erk_bk  = p[18]*ys[30]*ys[28] + p[19]*ys[28]*ys[33] + p[29]*ys[30]*ys[28];
    d[27] = -erk_fwd + erk_bk;
    d[28] =  erk_fwd - erk_bk;

    // --- DUSP / Sprouty feedback ---
    float denom_dusp = 1.0f + kmDuspRatio*ys[28];
    d[29] = p[27]*ys[28]/(denom_dusp + EPS) - p[21]*ys[29]*ys[36] - p[30]*ys[29]*ys[28];
    d[30] = -p[21]*ys[29]*ys[30];
    float denom_spry = 1.0f + kmSprtyRatio*ys[28];
    float spry_dn = p[24]*ys[31]*ys[32];
    d[31] = p[28]*ys[28]/(denom_spry + EPS) - spry_dn;
    d[32] = -spry_dn;
    d[33] = -p[19]*ys[28]*ys[33];
    d[34] = -mek_deg;
    d[35] = -craf_deg;
    d[36] = -p[21]*ys[29]*ys[36];

    // --- IGFR / IRS ---
    d[37] = -p[0]*ys[37] + p[1]*ys[38];
    d[38] =  p[0]*ys[37] - p[1]*ys[38] - p[2]*ys[38];
    d[39] =  p[2]*ys[38] - p[7]*ys[28]*ys[39];
    float erk_irs = p[68]*ys[28]*ys[41];
    float s6k_irs = p[71]*ys[66]*ys[41];
    float irs_fwd = p[0]*ys[2]*ys[40];
    d[40] = -irs_fwd + erk_irs + s6k_irs;
    d[41] =  irs_fwd - erk_irs - s6k_irs;

    // --- p85 binding ---
    float gab1 = 1.0f / (1.0f + p[72]*ys[28]);
    float bE  = p[33]*ys[2]*ys[42]*gab1;
    float bH2 = p[34]*ys[5]*ys[42]*gab1;
    float bH3 = p[35]*ys[8]*ys[42]*gab1;
    float bI  = p[36]*ys[39]*ys[42];
    float bP  = p[64]*ys[64]*ys[42];
    float sum_p85c = ys[43] + ys[44] + ys[45] + ys[46] + ys[67];
    float kunb = p[37];
    d[42] = -bE - bH2 - bH3 - bI - bP + kunb*sum_p85c;
    d[43] = bE  - kunb*ys[43];
    d[44] = bH2 - kunb*ys[44];
    d[45] = bH3 - kunb*ys[45];
    d[46] = bI  - kunb*ys[46];
    d[67] = bP  - kunb*ys[67];

    // --- PI3K / AKT / mTOR axis ---
    float pi3k_act = p[38]*sum_p85c*ys[47] + p[67]*ys[15]*ys[47];
    float mtor_fb  = p[39]*ys[56]*ys[48];
    d[47] = -pi3k_act + mtor_fb;
    d[48] =  pi3k_act - mtor_fb;
    float pip_fwd = p[40]*ys[48]*ys[49];
    float pip_rev = p[41]*ys[51]*ys[50];
    d[49] = -pip_fwd + pip_rev;
    d[50] =  pip_fwd - pip_rev;
    d[51] = p[69]*ys[28] - p[25]*ys[51];
    float akt_fwd = p[42]*ys[50]*ys[53];
    float akt_rev = p[43]*ys[52];
    d[52] =  akt_fwd - akt_rev;
    d[53] = -akt_fwd + akt_rev;
    float tsc = p[73]*ys[52]*ys[54];
    d[54] = -tsc;
    d[55] =  tsc - p[25]*ys[55];
    float mtor_fwd = p[44]*ys[52]*ys[57];
    float mtor_rev = p[45]*ys[56];
    d[56] =  mtor_fwd - mtor_rev;
    d[57] = -mtor_fwd + mtor_rev;
    float ebp_fwd = p[46]*ys[56]*ys[58];
    float ebp_rev = p[47]*ys[59];
    d[58] = -ebp_fwd + ebp_rev;
    d[59] =  ebp_fwd - ebp_rev;

    // --- KSR with trametinib hill factor ---
    float ksr_fwd = p[48]*ys[19]*ys[62]*tram_ksr;
    float ksr_rev = p[49]*ys[60];
    d[60] =  ksr_fwd - ksr_rev;
    d[62] = -ksr_fwd + ksr_rev;

    // --- PDGFR ---
    d[63] = -p[63]*ys[63];
    d[64] =  p[63]*ys[63] - p[6]*ys[64];

    // --- S6K ---
    float s6_fwd = p[65]*ys[56]*ys[65];
    float rsk    = p[74]*ys[28]*ys[65];
    float s6_rev = p[66]*ys[66];
    d[65] = -s6_fwd + s6_rev - rsk;
    d[66] =  s6_fwd - s6_rev + rsk;
}

__global__ __launch_bounds__(THREADS, 4)
void mapk_rhs_kernel(const float* __restrict__ y, const float* __restrict__ params,
                     float* __restrict__ out, int n) {
    // Per-warp float4 tile, column-major with stride 33 (conflict-free).
    __shared__ float4 stage[WARPS_PER_BLOCK][NF4 * COLSTRIDE];

    const int lane = threadIdx.x & 31;
    const int warp = threadIdx.x >> 5;
    const int rowStart = blockIdx.x * THREADS + warp * 32;
    if (rowStart >= n) return;
    const int rowsHere = min(32, n - rowStart);

    float4* sm = stage[warp];

    if (rowsHere == 32) {
        const float4* gsrc = reinterpret_cast<const float4*>(y) + (size_t)rowStart * NF4;

        // ---- Phase 1: coalesced LDG.128 -> transposed smem tile ----
        #pragma unroll
        for (int j = 0; j < NF4; j++) {
            int i = j * 32 + lane;          // f4 index within warp tile
            int r = i / NF4;
            int c = i - r * NF4;
            float4 v = __ldg(&gsrc[i]);
            v.x = fmaxf(v.x, 0.0f);
            v.y = fmaxf(v.y, 0.0f);
            v.z = fmaxf(v.z, 0.0f);
            v.w = fmaxf(v.w, 0.0f);
            sm[c * COLSTRIDE + r] = v;
        }
        __syncwarp();

        // ---- Phase 2: each thread owns row = lane; conflict-free smem access ----
        {
            float ys[NSTATE];
            float4* ysv = reinterpret_cast<float4*>(ys);
            #pragma unroll
            for (int c = 0; c < NF4; c++) ysv[c] = sm[c * COLSTRIDE + lane];

            float d[NSTATE];
            compute_rhs(params, ys, d);

            const float4* dv = reinterpret_cast<const float4*>(d);
            #pragma unroll
            for (int c = 0; c < NF4; c++) sm[c * COLSTRIDE + lane] = dv[c];
        }
        __syncwarp();

        // ---- Phase 3: transposed smem tile -> coalesced STG.128 ----
        float4* gdst = reinterpret_cast<float4*>(out) + (size_t)rowStart * NF4;
        #pragma unroll
        for (int j = 0; j < NF4; j++) {
            int i = j * 32 + lane;
            int r = i / NF4;
            int c = i - r * NF4;
            gdst[i] = sm[c * COLSTRIDE + r];
        }
    } else {
        // ---- Tail (rows < 32): direct per-row float4 access ----
        if (lane < rowsHere) {
            const int row = rowStart + lane;
            const float4* yv = reinterpret_cast<const float4*>(y) + (size_t)row * NF4;
            float ys[NSTATE];
            float4* ysv = reinterpret_cast<float4*>(ys);
            #pragma unroll
            for (int c = 0; c < NF4; c++) {
                float4 v = __ldg(&yv[c]);
                v.x = fmaxf(v.x, 0.0f);
                v.y = fmaxf(v.y, 0.0f);
                v.z = fmaxf(v.z, 0.0f);
                v.w = fmaxf(v.w, 0.0f);
                ysv[c] = v;
            }
            float d[NSTATE];
            compute_rhs(params, ys, d);
            float4* ov = reinterpret_cast<float4*>(out) + (size_t)row * NF4;
            const float4* dv = reinterpret_cast<const float4*>(d);
            #pragma unroll
            for (int c = 0; c < NF4; c++) ov[c] = dv[c];
        }
    }
}

extern "C" void kernel_launch(void* const* d_in, const int* in_sizes, int n_in,
                              void* d_out, int out_size) {
    // inputs per metadata order: t (1), y (B*68), params (75)
    const float* y      = (const float*)d_in[1];
    const float* params = (const float*)d_in[2];
    float* out = (float*)d_out;

    int n = in_sizes[1] / NSTATE;   // number of rows (B)

    int blocks = (n + THREADS - 1) / THREADS;
    mapk_rhs_kernel<<<blocks, THREADS>>>(y, params, out, n);
}